// round 6
// baseline (speedup 1.0000x reference)
#include <cuda_runtime.h>

// Hybrid quantum model, v5b: packed f32x2 with batch-pair lanes, 2-warp state
// pairs, analytic layer-0 (MPS product form), pre-broadcast gate tables,
// occupancy-5 single wave, single launch with last-CTA finalize.
// Fix vs v5: warp reduction actually sums (fadd2) instead of just shifting.

#define NC 320
typedef unsigned long long u64;

__device__ float g_acc[16];
__device__ unsigned int g_done;

#define CU_A (-0.2705980500730985f)
#define CU_B ( 0.6532814824381883f)
#define R2   ( 0.7071067811865476f)

// ---------------- packed f32x2 helpers ----------------
__device__ __forceinline__ u64 pack2(float x, float y) {
    u64 u; asm("mov.b64 %0,{%1,%2};" : "=l"(u) : "f"(x), "f"(y)); return u;
}
__device__ __forceinline__ float2 unpk(u64 u) {
    float2 v; asm("mov.b64 {%0,%1},%2;" : "=f"(v.x), "=f"(v.y) : "l"(u)); return v;
}
__device__ __forceinline__ u64 bc(float x) { return pack2(x, x); }
__device__ __forceinline__ u64 ffma2(u64 a, u64 b, u64 c) {
    u64 d; asm("fma.rn.f32x2 %0,%1,%2,%3;" : "=l"(d) : "l"(a), "l"(b), "l"(c)); return d;
}
__device__ __forceinline__ u64 fmul2(u64 a, u64 b) {
    u64 d; asm("mul.rn.f32x2 %0,%1,%2;" : "=l"(d) : "l"(a), "l"(b)); return d;
}
__device__ __forceinline__ u64 fadd2(u64 a, u64 b) {
    u64 d; asm("add.rn.f32x2 %0,%1,%2;" : "=l"(d) : "l"(a), "l"(b)); return d;
}
__device__ __forceinline__ u64 neg2(u64 a) { return a ^ 0x8000000080000000ull; }

__device__ __forceinline__ float2 cmul(float2 a, float2 b) {
    return make_float2(a.x*b.x - a.y*b.y, a.x*b.y + a.y*b.x);
}
__device__ __forceinline__ float2 cadd(float2 a, float2 b) {
    return make_float2(a.x + b.x, a.y + b.y);
}

// 8-const complex butterfly: negations inline (2 XOR -> alu pipe)
struct M8 { u64 x00,y00,x01,y01,x10,y10,x11,y11; };

__device__ __forceinline__ M8 loadM(const u64* p) {
    const ulonglong2* q = (const ulonglong2*)p;
    ulonglong2 a = q[0], b = q[1], c = q[2], d = q[3];
    M8 m; m.x00=a.x; m.y00=a.y; m.x01=b.x; m.y01=b.y;
          m.x10=c.x; m.y10=c.y; m.x11=d.x; m.y11=d.y;
    return m;
}
__device__ __forceinline__ void bfly8(u64& ar, u64& ai, u64& br, u64& bi, const M8& m) {
    u64 t1  = ffma2(m.y00, ai, fmul2(m.y01, bi));
    u64 nar = ffma2(m.x00, ar, ffma2(m.x01, br, neg2(t1)));
    u64 nai = ffma2(m.y00, ar, ffma2(m.x00, ai, ffma2(m.y01, br, fmul2(m.x01, bi))));
    u64 t2  = ffma2(m.y10, ai, fmul2(m.y11, bi));
    u64 nbr = ffma2(m.x10, ar, ffma2(m.x11, br, neg2(t2)));
    u64 nbi = ffma2(m.y10, ar, ffma2(m.x10, ai, ffma2(m.y11, br, fmul2(m.x11, bi))));
    ar=nar; ai=nai; br=nbr; bi=nbi;
}

// merged gate CU(c,t)*(I x R(t)): control=1 pairs get U*R, control=0 pairs get R
template<int CB, int TB>
__device__ __forceinline__ void merged_gate(u64* vr, u64* vi, const u64* pR, const u64* pUR) {
    {
        M8 m = loadM(pUR);
#pragma unroll
        for (int k = 0; k < 16; ++k)
            if ((k & CB) && !(k & TB))
                bfly8(vr[k], vi[k], vr[k|TB], vi[k|TB], m);
    }
    {
        M8 m = loadM(pR);
#pragma unroll
        for (int k = 0; k < 16; ++k)
            if (!(k & CB) && !(k & TB))
                bfly8(vr[k], vi[k], vr[k|TB], vi[k|TB], m);
    }
}

// MPS transfer factor for layer 0: target qubit in |+> before its gate.
// h(0,*) = 1/sqrt2 ; h(1,0) = (-A,-B) ; h(1,1) = (B,-A)
__device__ __forceinline__ float2 hfun(int xb, int yb) {
    if (xb == 0) return make_float2(R2, 0.0f);
    return yb ? make_float2(CU_B, -CU_A)
              : make_float2(-CU_A, -CU_B);
}

// swizzle on full 10-bit amp index (conflict-free for all 3 pass maps)
__device__ __forceinline__ unsigned sw(unsigned a) { return a ^ ((a >> 4) & 15u); }
// pass maps: amp index from (warp-bit, lane, reg)
__device__ __forceinline__ unsigned idxA(unsigned w, unsigned t, unsigned k) {
    return (k << 6) | (w << 5) | t;
}
__device__ __forceinline__ unsigned idxB(unsigned w, unsigned t, unsigned k) {
    return (w << 9) | ((t >> 3) << 7) | (k << 3) | (t & 7);
}
__device__ __forceinline__ unsigned idxC(unsigned w, unsigned t, unsigned k) {
    return (w << 9) | (t << 4) | k;
}

__global__ void __launch_bounds__(128, 5)
qsim_kernel(const float* __restrict__ x,  const float* __restrict__ W1,
            const float* __restrict__ b1, const float* __restrict__ qw,
            const float* __restrict__ W2, const float* __restrict__ b2,
            float* __restrict__ out)
{
    extern __shared__ u64 smem_u[];
    // [0,4096): state, pair p at p*2048 (re 1024, im 1024)
    // [4096,4384): Rbt[36][8]   [4384,4672): URbt[36][8]
    // then R0f[5][4] float2
    u64* Rbt  = smem_u + 4096;
    u64* URbt = smem_u + 4384;
    float2* R0f = (float2*)(smem_u + 4672);

    const int tid  = threadIdx.x;
    const int s    = tid >> 5;
    const int t    = tid & 31;
    const int p    = s >> 1;        // pair 0..1
    const int wbit = s & 1;
    const int c    = blockIdx.x >> 1;
    const int bh   = blockIdx.x & 1;
    const int b0   = bh*4 + p*2;    // lane0 batch
    const int b1i  = b0 + 1;        // lane1 batch
    const int barid = p + 1;

    u64* sre = smem_u + p * 2048;
    u64* sim = sre + 1024;

    // ---- tables: R_{l,q} and UR = U*R, pre-broadcast ----
    if (tid < 41) {
        int l = tid / 10, q = tid - l*10;   // tid 40 -> l=4,q=0
        const float* wp = qw + ((c*5 + l)*10 + q) * 3;
        float w0 = wp[0], w1v = wp[1], w2v = wp[2];
        float sy, cy; sincosf(0.5f * w1v,        &sy, &cy);
        float sp, cp; sincosf(0.5f * (w0 + w2v), &sp, &cp);
        float sm, cm; sincosf(0.5f * (w0 - w2v), &sm, &cm);
        float2 r00 = make_float2( cy*cp, -cy*sp);
        float2 r01 = make_float2(-sy*cm, -sy*sm);
        float2 r10 = make_float2( sy*cm, -sy*sm);
        float2 r11 = make_float2( cy*cp,  cy*sp);
        if (q == 0) {
            R0f[l*4+0] = r00; R0f[l*4+1] = r01; R0f[l*4+2] = r10; R0f[l*4+3] = r11;
        } else {
            int idx = (l*9 + q - 1) * 8;
            Rbt[idx+0]=bc(r00.x); Rbt[idx+1]=bc(r00.y);
            Rbt[idx+2]=bc(r01.x); Rbt[idx+3]=bc(r01.y);
            Rbt[idx+4]=bc(r10.x); Rbt[idx+5]=bc(r10.y);
            Rbt[idx+6]=bc(r11.x); Rbt[idx+7]=bc(r11.y);
            const float2 u00 = make_float2(CU_A,  CU_A);
            const float2 u01 = make_float2(CU_B, -CU_B);
            const float2 u10 = make_float2(CU_B,  CU_B);
            const float2 u11 = make_float2(-CU_A, CU_A);
            float2 s00 = cadd(cmul(u00, r00), cmul(u01, r10));
            float2 s01 = cadd(cmul(u00, r01), cmul(u01, r11));
            float2 s10 = cadd(cmul(u10, r00), cmul(u11, r10));
            float2 s11 = cadd(cmul(u10, r01), cmul(u11, r11));
            URbt[idx+0]=bc(s00.x); URbt[idx+1]=bc(s00.y);
            URbt[idx+2]=bc(s01.x); URbt[idx+3]=bc(s01.y);
            URbt[idx+4]=bc(s10.x); URbt[idx+5]=bc(s10.y);
            URbt[idx+6]=bc(s11.x); URbt[idx+7]=bc(s11.y);
        }
    }

    // ---- embedding angles (2 batch lanes) ----
    float h0 = x[b0*2+0]*W1[c*2+0] + x[b0*2+1]*W1[c*2+1] + b1[c];
    float h1 = x[b1i*2+0]*W1[c*2+0] + x[b1i*2+1]*W1[c*2+1] + b1[c];
    float se0, ce0, se1, ce1;
    sincosf(0.5f * h0, &se0, &ce0);
    sincosf(0.5f * h1, &se1, &ce1);

    u64 vr[16], vi[16];

    // ---- analytic layer 0: amp = E(b0) * prod h(bj,bj+1), built in pass-A layout ----
    {
        float2 P = hfun(wbit, (t>>4)&1);
        P = cmul(P, hfun((t>>4)&1, (t>>3)&1));
        P = cmul(P, hfun((t>>3)&1, (t>>2)&1));
        P = cmul(P, hfun((t>>2)&1, (t>>1)&1));
        P = cmul(P, hfun((t>>1)&1,  t&1));
        u64 E0 = pack2((ce0 - se0)*R2, (ce1 - se1)*R2);
        u64 E1 = pack2((ce0 + se0)*R2, (ce1 + se1)*R2);
        u64 Px = bc(P.x), Py = bc(P.y);
        u64 EP0r = fmul2(E0, Px), EP0i = fmul2(E0, Py);
        u64 EP1r = fmul2(E1, Px), EP1i = fmul2(E1, Py);
#pragma unroll
        for (int k = 0; k < 16; ++k) {
            int k3 = (k>>3)&1, k2 = (k>>2)&1, k1b = (k>>1)&1, k0 = k&1;
            float2 K = cmul(cmul(hfun(k3,k2), hfun(k2,k1b)),
                            cmul(hfun(k1b,k0), hfun(k0,wbit)));
            u64 kx = bc(K.x), ky = bc(K.y);
            u64 epr = k3 ? EP1r : EP0r;
            u64 epi = k3 ? EP1i : EP0i;
            vr[k] = ffma2(kx, epr, fmul2(neg2(ky), epi));
            vi[k] = ffma2(kx, epi, fmul2(ky, epr));
        }
    }

    __syncthreads();   // tables visible

#pragma unroll 1
    for (int l = 1; l <= 4; ++l) {
        const u64* Rb  = Rbt  + (l-1)*9*8;
        const u64* URb = URbt + (l-1)*9*8;

        // ===== Pass A: k = amp bits 9-6 (qubits 0-3) =====
        if (l > 1) {
#pragma unroll
            for (int k = 0; k < 16; ++k) { unsigned j = sw(idxA(wbit,t,k)); vr[k]=sre[j]; vi[k]=sim[j]; }
        }
        {   // merged embedding: E' = emb_l * R_{l-1,0}, per-lane
            float2 r00 = R0f[(l-1)*4+0], r01 = R0f[(l-1)*4+1];
            float2 r10 = R0f[(l-1)*4+2], r11 = R0f[(l-1)*4+3];
            float2 eA[4], eB[4];
            if ((l & 1) == 0) {  // RY
                eA[0]=make_float2(ce0*r00.x-se0*r10.x, ce0*r00.y-se0*r10.y);
                eA[1]=make_float2(ce0*r01.x-se0*r11.x, ce0*r01.y-se0*r11.y);
                eA[2]=make_float2(se0*r00.x+ce0*r10.x, se0*r00.y+ce0*r10.y);
                eA[3]=make_float2(se0*r01.x+ce0*r11.x, se0*r01.y+ce0*r11.y);
                eB[0]=make_float2(ce1*r00.x-se1*r10.x, ce1*r00.y-se1*r10.y);
                eB[1]=make_float2(ce1*r01.x-se1*r11.x, ce1*r01.y-se1*r11.y);
                eB[2]=make_float2(se1*r00.x+ce1*r10.x, se1*r00.y+ce1*r10.y);
                eB[3]=make_float2(se1*r01.x+ce1*r11.x, se1*r01.y+ce1*r11.y);
            } else {             // RZ
                float2 f0a=make_float2(ce0,-se0), f1a=make_float2(ce0,se0);
                float2 f0b=make_float2(ce1,-se1), f1b=make_float2(ce1,se1);
                eA[0]=cmul(f0a,r00); eA[1]=cmul(f0a,r01); eA[2]=cmul(f1a,r10); eA[3]=cmul(f1a,r11);
                eB[0]=cmul(f0b,r00); eB[1]=cmul(f0b,r01); eB[2]=cmul(f1b,r10); eB[3]=cmul(f1b,r11);
            }
            M8 pm;
            pm.x00=pack2(eA[0].x,eB[0].x); pm.y00=pack2(eA[0].y,eB[0].y);
            pm.x01=pack2(eA[1].x,eB[1].x); pm.y01=pack2(eA[1].y,eB[1].y);
            pm.x10=pack2(eA[2].x,eB[2].x); pm.y10=pack2(eA[2].y,eB[2].y);
            pm.x11=pack2(eA[3].x,eB[3].x); pm.y11=pack2(eA[3].y,eB[3].y);
#pragma unroll
            for (int k = 0; k < 8; ++k)
                bfly8(vr[k], vi[k], vr[k+8], vi[k+8], pm);
        }
        merged_gate<8,4>(vr, vi, Rb + 0*8, URb + 0*8);   // cu(0,1)+R1
        merged_gate<4,2>(vr, vi, Rb + 1*8, URb + 1*8);   // cu(1,2)+R2
        merged_gate<2,1>(vr, vi, Rb + 2*8, URb + 2*8);   // cu(2,3)+R3
#pragma unroll
        for (int k = 0; k < 16; ++k) { unsigned j = sw(idxA(wbit,t,k)); sre[j]=vr[k]; sim[j]=vi[k]; }
        asm volatile("bar.sync %0, %1;" :: "r"(barid), "r"(64) : "memory");

        // ===== Pass B: k = amp bits 6-3 (qubits 3-6) =====
#pragma unroll
        for (int k = 0; k < 16; ++k) { unsigned j = sw(idxB(wbit,t,k)); vr[k]=sre[j]; vi[k]=sim[j]; }
        merged_gate<8,4>(vr, vi, Rb + 3*8, URb + 3*8);   // cu(3,4)+R4
        merged_gate<4,2>(vr, vi, Rb + 4*8, URb + 4*8);   // cu(4,5)+R5
        merged_gate<2,1>(vr, vi, Rb + 5*8, URb + 5*8);   // cu(5,6)+R6
#pragma unroll
        for (int k = 0; k < 16; ++k) { unsigned j = sw(idxB(wbit,t,k)); sre[j]=vr[k]; sim[j]=vi[k]; }
        asm volatile("bar.sync %0, %1;" :: "r"(barid), "r"(64) : "memory");

        // ===== Pass C: k = amp bits 3-0 (qubits 6-9) =====
#pragma unroll
        for (int k = 0; k < 16; ++k) { unsigned j = sw(idxC(wbit,t,k)); vr[k]=sre[j]; vi[k]=sim[j]; }
        merged_gate<8,4>(vr, vi, Rb + 6*8, URb + 6*8);   // cu(6,7)+R7
        merged_gate<4,2>(vr, vi, Rb + 7*8, URb + 7*8);   // cu(7,8)+R8
        merged_gate<2,1>(vr, vi, Rb + 8*8, URb + 8*8);   // cu(8,9)+R9
#pragma unroll
        for (int k = 0; k < 16; ++k) { unsigned j = sw(idxC(wbit,t,k)); sre[j]=vr[k]; sim[j]=vi[k]; }
        asm volatile("bar.sync %0, %1;" :: "r"(barid), "r"(64) : "memory");
    }

    // ===== Measurement: <Z0>, trailing qubit-0 gate G = H * R40 * R40 =====
#pragma unroll
    for (int k = 0; k < 16; ++k) { unsigned j = sw(idxA(wbit,t,k)); vr[k]=sre[j]; vi[k]=sim[j]; }
    {
        float2 r00 = R0f[16], r01 = R0f[17], r10 = R0f[18], r11 = R0f[19];
        float2 s00 = cadd(cmul(r00,r00), cmul(r01,r10));
        float2 s01 = cadd(cmul(r00,r01), cmul(r01,r11));
        float2 s10 = cadd(cmul(r10,r00), cmul(r11,r10));
        float2 s11 = cadd(cmul(r10,r01), cmul(r11,r11));
        float2 g00 = make_float2(R2*(s00.x+s10.x), R2*(s00.y+s10.y));
        float2 g01 = make_float2(R2*(s01.x+s11.x), R2*(s01.y+s11.y));
        float2 g10 = make_float2(R2*(s00.x-s10.x), R2*(s00.y-s10.y));
        float2 g11 = make_float2(R2*(s01.x-s11.x), R2*(s01.y-s11.y));
        M8 gm;
        gm.x00=bc(g00.x); gm.y00=bc(g00.y); gm.x01=bc(g01.x); gm.y01=bc(g01.y);
        gm.x10=bc(g10.x); gm.y10=bc(g10.y); gm.x11=bc(g11.x); gm.y11=bc(g11.y);
        u64 acc = bc(0.0f);
#pragma unroll
        for (int k = 0; k < 8; ++k) {
            bfly8(vr[k], vi[k], vr[k|8], vi[k|8], gm);
            acc = ffma2(vr[k], vr[k], acc);
            acc = ffma2(vi[k], vi[k], acc);
            acc = ffma2(neg2(vr[k|8]), vr[k|8], acc);
            acc = ffma2(neg2(vi[k|8]), vi[k|8], acc);
        }
#pragma unroll
        for (int off = 16; off > 0; off >>= 1)
            acc = fadd2(acc, __shfl_down_sync(0xffffffffu, acc, off));
        if (t == 0) {
            float2 z = unpk(acc);
            float w2a = W2[c], w2b = W2[NC + c];
            atomicAdd(&g_acc[b0*2  + 0], z.x * w2a);
            atomicAdd(&g_acc[b0*2  + 1], z.x * w2b);
            atomicAdd(&g_acc[b1i*2 + 0], z.y * w2a);
            atomicAdd(&g_acc[b1i*2 + 1], z.y * w2b);
        }
    }
    __syncthreads();

    // last CTA finalizes: softmax + output + reset
    if (tid == 0) {
        __threadfence();
        unsigned int done = atomicAdd(&g_done, 1u);
        if (done == gridDim.x - 1) {
            __threadfence();
#pragma unroll
            for (int bb = 0; bb < 8; ++bb) {
                float l0 = g_acc[2*bb]   + b2[0];
                float l1 = g_acc[2*bb+1] + b2[1];
                float m  = fmaxf(l0, l1);
                float e0 = expf(l0 - m), e1 = expf(l1 - m);
                float inv = 1.0f / (e0 + e1);
                out[2*bb + 0] = e0 * inv;
                out[2*bb + 1] = e1 * inv;
                g_acc[2*bb]   = 0.0f;
                g_acc[2*bb+1] = 0.0f;
            }
            g_done = 0u;
            __threadfence();
        }
    }
}

extern "C" void kernel_launch(void* const* d_in, const int* in_sizes, int n_in,
                              void* d_out, int out_size) {
    const float* x  = (const float*)d_in[0];   // (8,2)
    const float* W1 = (const float*)d_in[1];   // (320,2)
    const float* b1 = (const float*)d_in[2];   // (320,)
    const float* qw = (const float*)d_in[3];   // (320,5,10,3)
    const float* W2 = (const float*)d_in[4];   // (2,320)
    const float* b2 = (const float*)d_in[5];   // (2,)
    float* out = (float*)d_out;                // (8,2)

    const int smem = 4672 * sizeof(unsigned long long) + 20 * sizeof(float2);
    cudaFuncSetAttribute(qsim_kernel, cudaFuncAttributeMaxDynamicSharedMemorySize, smem);
    qsim_kernel<<<640, 128, smem>>>(x, W1, b1, qw, W2, b2, out);
}

// round 7
// speedup vs baseline: 1.3669x; 1.3669x over previous
#include <cuda_runtime.h>

// Hybrid quantum model, v6: v4 structure (packed f32x2, warp-private states,
// merged rot-into-CU gates, regs<=128/occ4) + analytic layer-0 (MPS product
// form, validated in v5b). Single launch, last-CTA finalize.

#define NC   320

typedef unsigned long long u64;

__device__ float g_acc[16];          // partial logits [batch][2]
__device__ unsigned int g_done;      // CTA completion counter

#define CU_A (-0.2705980500730985f)
#define CU_B ( 0.6532814824381883f)
#define R2   ( 0.7071067811865476f)

// ---------------- packed f32x2 helpers ----------------
__device__ __forceinline__ u64 pack2(float x, float y) {
    u64 u; asm("mov.b64 %0,{%1,%2};" : "=l"(u) : "f"(x), "f"(y)); return u;
}
__device__ __forceinline__ float2 unpk(u64 u) {
    float2 v; asm("mov.b64 {%0,%1},%2;" : "=f"(v.x), "=f"(v.y) : "l"(u)); return v;
}
__device__ __forceinline__ u64 bc(float x) { return pack2(x, x); }
__device__ __forceinline__ u64 ffma2(u64 a, u64 b, u64 c) {
    u64 d; asm("fma.rn.f32x2 %0,%1,%2,%3;" : "=l"(d) : "l"(a), "l"(b), "l"(c)); return d;
}
__device__ __forceinline__ u64 fmul2(u64 a, u64 b) {
    u64 d; asm("mul.rn.f32x2 %0,%1,%2;" : "=l"(d) : "l"(a), "l"(b)); return d;
}
__device__ __forceinline__ u64 neg2(u64 a) { return a ^ 0x8000000080000000ull; }

__device__ __forceinline__ float2 cmul(float2 a, float2 b) {
    return make_float2(a.x*b.x - a.y*b.y, a.x*b.y + a.y*b.x);
}
__device__ __forceinline__ float2 cadd(float2 a, float2 b) {
    return make_float2(a.x + b.x, a.y + b.y);
}

// general complex 2x2 butterfly on packed pairs
struct M12 { u64 x00,y00,yn00,x01,y01,yn01,x10,y10,yn10,x11,y11,yn11; };

__device__ __forceinline__ M12 mkM(float2 m00, float2 m01, float2 m10, float2 m11) {
    M12 m;
    m.x00=bc(m00.x); m.y00=bc(m00.y); m.yn00=bc(-m00.y);
    m.x01=bc(m01.x); m.y01=bc(m01.y); m.yn01=bc(-m01.y);
    m.x10=bc(m10.x); m.y10=bc(m10.y); m.yn10=bc(-m10.y);
    m.x11=bc(m11.x); m.y11=bc(m11.y); m.yn11=bc(-m11.y);
    return m;
}
__device__ __forceinline__ void bfly(u64& ar, u64& ai, u64& br, u64& bi, const M12& m) {
    u64 nar = ffma2(m.x00,ar, ffma2(m.yn00,ai, ffma2(m.x01,br, fmul2(m.yn01,bi))));
    u64 nai = ffma2(m.y00,ar, ffma2(m.x00, ai, ffma2(m.y01,br, fmul2(m.x01, bi))));
    u64 nbr = ffma2(m.x10,ar, ffma2(m.yn10,ai, ffma2(m.x11,br, fmul2(m.yn11,bi))));
    u64 nbi = ffma2(m.y10,ar, ffma2(m.x10, ai, ffma2(m.y11,br, fmul2(m.x11, bi))));
    ar=nar; ai=nai; br=nbr; bi=nbi;
}

// merged gate CU(c,t) * (I ⊗ R(t)): control=1 pairs get U·R, control=0 pairs get R
template<int CB, int TB>
__device__ __forceinline__ void merged_cu(u64* vr, u64* vi, const float2* pR, const float2* pUR) {
    {
        M12 m = mkM(pUR[0], pUR[1], pUR[2], pUR[3]);
#pragma unroll
        for (int k = 0; k < 16; ++k)
            if (!(k & TB) && (k & CB))
                bfly(vr[k], vi[k], vr[k|TB], vi[k|TB], m);
    }
    {
        M12 m = mkM(pR[0], pR[1], pR[2], pR[3]);
#pragma unroll
        for (int k = 0; k < 16; ++k)
            if (!(k & TB) && !(k & CB))
                bfly(vr[k], vi[k], vr[k|TB], vi[k|TB], m);
    }
}

// lane-mixing scalar butterfly (target = packed lane = amp bit0)
__device__ __forceinline__ void lane_bfly(u64& r, u64& i,
        float x00, float y00, float x01, float y01,
        float x10, float y10, float x11, float y11) {
    float2 rr = unpk(r), ii = unpk(i);
    float ax = rr.x, bx = rr.y, ay = ii.x, by = ii.y;
    float nax = x00*ax - y00*ay + x01*bx - y01*by;
    float nay = y00*ax + x00*ay + y01*bx + x01*by;
    float nbx = x10*ax - y10*ay + x11*bx - y11*by;
    float nby = y10*ax + x10*ay + y11*bx + x11*by;
    r = pack2(nax, nbx); i = pack2(nay, nby);
}
__device__ __forceinline__ void lane_bfly_m(u64& r, u64& i, const float2* p) {
    lane_bfly(r, i, p[0].x,p[0].y, p[1].x,p[1].y, p[2].x,p[2].y, p[3].x,p[3].y);
}

// MPS transfer factor for layer 0 (validated in v5b):
// h(0,*) = 1/sqrt2 ; h(1,0) = (-A,-B) ; h(1,1) = (B,-A)
__device__ __forceinline__ float2 hfun(int xb, int yb) {
    if (xb == 0) return make_float2(R2, 0.0f);
    return yb ? make_float2(CU_B, -CU_A)
              : make_float2(-CU_A, -CU_B);
}

__device__ __forceinline__ unsigned sw(unsigned i) { return i ^ ((i >> 4) & 15u); }
__device__ __forceinline__ unsigned idxA(unsigned t, unsigned k) { return (k << 5) | t; }
__device__ __forceinline__ unsigned idxB(unsigned t, unsigned k) { return ((t >> 2) << 6) | (k << 2) | (t & 3); }
__device__ __forceinline__ unsigned idxC(unsigned t, unsigned k) { return (t << 4) | k; }

__global__ void __launch_bounds__(128, 4)
qsim_kernel(const float* __restrict__ x,  const float* __restrict__ W1,
            const float* __restrict__ b1, const float* __restrict__ qw,
            const float* __restrict__ W2, const float* __restrict__ b2,
            float* __restrict__ out)
{
    extern __shared__ u64 smem_u[];
    const int tid = threadIdx.x;
    const int s   = tid >> 5;           // warp 0..3
    const int t   = tid & 31;
    const int c   = blockIdx.x >> 1;    // circuit
    const int b   = (blockIdx.x & 1) * 4 + s;  // batch row 0..7

    u64* sre  = smem_u + s * 512;
    u64* simm = smem_u + 2048 + s * 512;
    float2* Rm  = (float2*)(smem_u + 4096);  // [50][4]
    float2* URm = Rm + 200;                  // [40][4]  (l=0..3, q=0..9; q0 unused)

    // R_{l,q} = RZ(w2) RY(w1) RZ(w0)
    if (tid < 50) {
        int l = tid / 10, q = tid - l * 10;
        const float* wp = qw + ((c*5 + l)*10 + q) * 3;
        float w0 = wp[0], w1v = wp[1], w2v = wp[2];
        float sy, cy; sincosf(0.5f * w1v,        &sy, &cy);
        float sp, cp; sincosf(0.5f * (w0 + w2v), &sp, &cp);
        float sm, cm; sincosf(0.5f * (w0 - w2v), &sm, &cm);
        Rm[tid*4+0] = make_float2( cy*cp, -cy*sp);
        Rm[tid*4+1] = make_float2(-sy*cm, -sy*sm);
        Rm[tid*4+2] = make_float2( sy*cm, -sy*sm);
        Rm[tid*4+3] = make_float2( cy*cp,  cy*sp);
    }
    __syncthreads();
    // UR_{l,q} = U * R_{l,q}
    if (tid < 40 && (tid % 10) != 0) {
        const float2 u00 = make_float2(CU_A,  CU_A);
        const float2 u01 = make_float2(CU_B, -CU_B);
        const float2 u10 = make_float2(CU_B,  CU_B);
        const float2 u11 = make_float2(-CU_A, CU_A);
        float2 r00 = Rm[tid*4+0], r01 = Rm[tid*4+1], r10 = Rm[tid*4+2], r11 = Rm[tid*4+3];
        URm[tid*4+0] = cadd(cmul(u00, r00), cmul(u01, r10));
        URm[tid*4+1] = cadd(cmul(u00, r01), cmul(u01, r11));
        URm[tid*4+2] = cadd(cmul(u10, r00), cmul(u11, r10));
        URm[tid*4+3] = cadd(cmul(u10, r01), cmul(u11, r11));
    }

    float hang = x[b*2+0]*W1[c*2+0] + x[b*2+1]*W1[c*2+1] + b1[c];
    float se, ce;
    sincosf(0.5f * hang, &se, &ce);

    u64 vr[16], vi[16];

    // ---- analytic layer 0 in pass-A layout ----
    // amp bits: b9..b6 = k3..k0, b5..b1 = t4..t0, b0 = packed lane
    // amp = E(b9) * h(b9,b8) h(b8,b7) ... h(b1,b0)
    {
        float2 Tc = cmul(cmul(hfun((t>>4)&1,(t>>3)&1), hfun((t>>3)&1,(t>>2)&1)),
                         cmul(hfun((t>>2)&1,(t>>1)&1), hfun((t>>1)&1, t&1)));
        float2 L0 = hfun(t&1, 0), L1 = hfun(t&1, 1);
        float2 T0 = cmul(Tc, L0), T1 = cmul(Tc, L1);
        u64 Tr = pack2(T0.x, T1.x), Ti = pack2(T0.y, T1.y);
        float E0 = (ce - se) * R2, E1 = (ce + se) * R2;
        int t4 = (t >> 4) & 1;
#pragma unroll
        for (int k = 0; k < 16; ++k) {
            int k3 = (k>>3)&1, k2 = (k>>2)&1, k1b = (k>>1)&1, k0 = k&1;
            float2 K = cmul(cmul(hfun(k3,k2), hfun(k2,k1b)),
                            cmul(hfun(k1b,k0), hfun(k0,t4)));
            float Ek = k3 ? E1 : E0;
            K.x *= Ek; K.y *= Ek;
            u64 kx = bc(K.x), ky = bc(K.y);
            vr[k] = ffma2(kx, Tr, fmul2(neg2(ky), Ti));
            vi[k] = ffma2(kx, Ti, fmul2(ky, Tr));
        }
    }

    __syncthreads();   // tables visible

#pragma unroll 1
    for (int l = 1; l <= 4; ++l) {
        const float2* Rp  = Rm  + (l-1)*40;
        const float2* URp = URm + (l-1)*40;

        // ===== Pass A: qubits 0-3 =====
        if (l > 1) {
#pragma unroll
            for (int k = 0; k < 16; ++k) { unsigned j = sw(idxA(t,k)); vr[k]=sre[j]; vi[k]=simm[j]; }
        }
        {   // merged embedding: E' = emb_l * R_{l-1,0}
            float2 r00 = Rp[0], r01 = Rp[1], r10 = Rp[2], r11 = Rp[3];
            float2 e00, e01, e10, e11;
            if ((l & 1) == 0) {  // RY (real)
                e00 = make_float2(ce*r00.x - se*r10.x, ce*r00.y - se*r10.y);
                e01 = make_float2(ce*r01.x - se*r11.x, ce*r01.y - se*r11.y);
                e10 = make_float2(se*r00.x + ce*r10.x, se*r00.y + ce*r10.y);
                e11 = make_float2(se*r01.x + ce*r11.x, se*r01.y + ce*r11.y);
            } else {             // RZ diag((ce,-se),(ce,se))
                float2 f0 = make_float2(ce, -se), f1 = make_float2(ce, se);
                e00 = cmul(f0, r00); e01 = cmul(f0, r01);
                e10 = cmul(f1, r10); e11 = cmul(f1, r11);
            }
            M12 me = mkM(e00, e01, e10, e11);
#pragma unroll
            for (int k = 0; k < 8; ++k)
                bfly(vr[k], vi[k], vr[k+8], vi[k+8], me);
        }
        merged_cu<8,4>(vr, vi, Rp + 1*4, URp + 1*4);   // cu(0,1)+R1
        merged_cu<4,2>(vr, vi, Rp + 2*4, URp + 2*4);   // cu(1,2)+R2
        merged_cu<2,1>(vr, vi, Rp + 3*4, URp + 3*4);   // cu(2,3)+R3
#pragma unroll
        for (int k = 0; k < 16; ++k) { unsigned j = sw(idxA(t,k)); sre[j]=vr[k]; simm[j]=vi[k]; }
        __syncwarp();

        // ===== Pass B: qubits 3-6 =====
#pragma unroll
        for (int k = 0; k < 16; ++k) { unsigned j = sw(idxB(t,k)); vr[k]=sre[j]; vi[k]=simm[j]; }
        merged_cu<8,4>(vr, vi, Rp + 4*4, URp + 4*4);   // cu(3,4)+R4
        merged_cu<4,2>(vr, vi, Rp + 5*4, URp + 5*4);   // cu(4,5)+R5
        merged_cu<2,1>(vr, vi, Rp + 6*4, URp + 6*4);   // cu(5,6)+R6
#pragma unroll
        for (int k = 0; k < 16; ++k) { unsigned j = sw(idxB(t,k)); sre[j]=vr[k]; simm[j]=vi[k]; }
        __syncwarp();

        // ===== Pass C: qubits 6-9 (lane = qubit 9) =====
#pragma unroll
        for (int k = 0; k < 16; ++k) { unsigned j = sw(idxC(t,k)); vr[k]=sre[j]; vi[k]=simm[j]; }
        merged_cu<4,2>(vr, vi, Rp + 7*4, URp + 7*4);   // cu(6,7)+R7
        merged_cu<2,1>(vr, vi, Rp + 8*4, URp + 8*4);   // cu(7,8)+R8
        // merged cu(8,9): control = k bit0, target = lane
#pragma unroll
        for (int k = 0; k < 16; ++k) {
            if (k & 1) lane_bfly_m(vr[k], vi[k], URp + 9*4);
            else       lane_bfly_m(vr[k], vi[k], Rp  + 9*4);
        }
#pragma unroll
        for (int k = 0; k < 16; ++k) { unsigned j = sw(idxC(t,k)); sre[j]=vr[k]; simm[j]=vi[k]; }
        __syncwarp();
    }

    // ===== Measurement: <Z0>, trailing qubit-0 gate G = H * R40 * R40 =====
#pragma unroll
    for (int k = 0; k < 16; ++k) { unsigned j = sw(idxA(t,k)); vr[k]=sre[j]; vi[k]=simm[j]; }
    float z;
    {
        float2 r00 = Rm[160], r01 = Rm[161], r10 = Rm[162], r11 = Rm[163];
        float2 s00 = cadd(cmul(r00,r00), cmul(r01,r10));
        float2 s01 = cadd(cmul(r00,r01), cmul(r01,r11));
        float2 s10 = cadd(cmul(r10,r00), cmul(r11,r10));
        float2 s11 = cadd(cmul(r10,r01), cmul(r11,r11));
        float2 g00 = make_float2(R2*(s00.x+s10.x), R2*(s00.y+s10.y));
        float2 g01 = make_float2(R2*(s01.x+s11.x), R2*(s01.y+s11.y));
        float2 g10 = make_float2(R2*(s00.x-s10.x), R2*(s00.y-s10.y));
        float2 g11 = make_float2(R2*(s01.x-s11.x), R2*(s01.y-s11.y));
        M12 gm = mkM(g00, g01, g10, g11);
        u64 acc = bc(0.0f);
#pragma unroll
        for (int k = 0; k < 8; ++k) {
            bfly(vr[k], vi[k], vr[k|8], vi[k|8], gm);
            acc = ffma2(vr[k],   vr[k],   acc);
            acc = ffma2(vi[k],   vi[k],   acc);
            acc = ffma2(neg2(vr[k|8]), vr[k|8], acc);
            acc = ffma2(neg2(vi[k|8]), vi[k|8], acc);
        }
        float2 av = unpk(acc);
        z = av.x + av.y;
#pragma unroll
        for (int off = 16; off > 0; off >>= 1) z += __shfl_down_sync(0xffffffffu, z, off);
    }
    if (t == 0) {
        atomicAdd(&g_acc[b*2 + 0], z * W2[c]);
        atomicAdd(&g_acc[b*2 + 1], z * W2[NC + c]);
    }
    __syncthreads();

    // last CTA finalizes: softmax + output + reset
    if (tid == 0) {
        __threadfence();
        unsigned int done = atomicAdd(&g_done, 1u);
        if (done == gridDim.x - 1) {
            __threadfence();
#pragma unroll
            for (int bb = 0; bb < 8; ++bb) {
                float l0 = g_acc[2*bb]   + b2[0];
                float l1 = g_acc[2*bb+1] + b2[1];
                float m  = fmaxf(l0, l1);
                float e0 = expf(l0 - m), e1 = expf(l1 - m);
                float inv = 1.0f / (e0 + e1);
                out[2*bb + 0] = e0 * inv;
                out[2*bb + 1] = e1 * inv;
                g_acc[2*bb]   = 0.0f;
                g_acc[2*bb+1] = 0.0f;
            }
            g_done = 0u;
            __threadfence();
        }
    }
}

extern "C" void kernel_launch(void* const* d_in, const int* in_sizes, int n_in,
                              void* d_out, int out_size) {
    const float* x  = (const float*)d_in[0];   // (8,2)
    const float* W1 = (const float*)d_in[1];   // (320,2)
    const float* b1 = (const float*)d_in[2];   // (320,)
    const float* qw = (const float*)d_in[3];   // (320,5,10,3)
    const float* W2 = (const float*)d_in[4];   // (2,320)
    const float* b2 = (const float*)d_in[5];   // (2,)
    float* out = (float*)d_out;                // (8,2)

    const int smem = 4096 * sizeof(unsigned long long) + 360 * sizeof(float2);
    cudaFuncSetAttribute(qsim_kernel, cudaFuncAttributeMaxDynamicSharedMemorySize, smem);
    qsim_kernel<<<640, 128, smem>>>(x, W1, b1, qw, W2, b2, out);
}

// round 8
// speedup vs baseline: 2.6576x; 1.9442x over previous
#include <cuda_runtime.h>

// Hybrid quantum model, v7: light-cone pruned circuit. Observable Z0's causal
// cone keeps only 14/40 merged gates, all on qubits 0-4 (= register bits +
// one lane bit). Entire evolution happens in registers: analytic layer-0 init
// (MPS product form) -> 4 pruned layers -> in-register measurement. No state
// SMEM, no transposes, no barriers (one table sync). Single launch.

#define NC   320

typedef unsigned long long u64;

__device__ float g_acc[16];          // partial logits [batch][2]
__device__ unsigned int g_done;      // CTA completion counter

#define CU_A (-0.2705980500730985f)
#define CU_B ( 0.6532814824381883f)
#define R2   ( 0.7071067811865476f)

// ---------------- packed f32x2 helpers ----------------
__device__ __forceinline__ u64 pack2(float x, float y) {
    u64 u; asm("mov.b64 %0,{%1,%2};" : "=l"(u) : "f"(x), "f"(y)); return u;
}
__device__ __forceinline__ float2 unpk(u64 u) {
    float2 v; asm("mov.b64 {%0,%1},%2;" : "=f"(v.x), "=f"(v.y) : "l"(u)); return v;
}
__device__ __forceinline__ u64 bc(float x) { return pack2(x, x); }
__device__ __forceinline__ u64 ffma2(u64 a, u64 b, u64 c) {
    u64 d; asm("fma.rn.f32x2 %0,%1,%2,%3;" : "=l"(d) : "l"(a), "l"(b), "l"(c)); return d;
}
__device__ __forceinline__ u64 fmul2(u64 a, u64 b) {
    u64 d; asm("mul.rn.f32x2 %0,%1,%2;" : "=l"(d) : "l"(a), "l"(b)); return d;
}
__device__ __forceinline__ u64 neg2(u64 a) { return a ^ 0x8000000080000000ull; }

__device__ __forceinline__ float2 cmul(float2 a, float2 b) {
    return make_float2(a.x*b.x - a.y*b.y, a.x*b.y + a.y*b.x);
}
__device__ __forceinline__ float2 cadd(float2 a, float2 b) {
    return make_float2(a.x + b.x, a.y + b.y);
}

// general complex 2x2 butterfly on packed pairs
struct M12 { u64 x00,y00,yn00,x01,y01,yn01,x10,y10,yn10,x11,y11,yn11; };

__device__ __forceinline__ M12 mkM(float2 m00, float2 m01, float2 m10, float2 m11) {
    M12 m;
    m.x00=bc(m00.x); m.y00=bc(m00.y); m.yn00=bc(-m00.y);
    m.x01=bc(m01.x); m.y01=bc(m01.y); m.yn01=bc(-m01.y);
    m.x10=bc(m10.x); m.y10=bc(m10.y); m.yn10=bc(-m10.y);
    m.x11=bc(m11.x); m.y11=bc(m11.y); m.yn11=bc(-m11.y);
    return m;
}
__device__ __forceinline__ void bfly(u64& ar, u64& ai, u64& br, u64& bi, const M12& m) {
    u64 nar = ffma2(m.x00,ar, ffma2(m.yn00,ai, ffma2(m.x01,br, fmul2(m.yn01,bi))));
    u64 nai = ffma2(m.y00,ar, ffma2(m.x00, ai, ffma2(m.y01,br, fmul2(m.x01, bi))));
    u64 nbr = ffma2(m.x10,ar, ffma2(m.yn10,ai, ffma2(m.x11,br, fmul2(m.yn11,bi))));
    u64 nbi = ffma2(m.y10,ar, ffma2(m.x10, ai, ffma2(m.y11,br, fmul2(m.x11, bi))));
    ar=nar; ai=nai; br=nbr; bi=nbi;
}

// merged gate CU(c,t)*(I⊗R(t)): control=1 pairs get U·R, control=0 pairs get R
template<int CB, int TB>
__device__ __forceinline__ void merged_cu(u64* vr, u64* vi, const float2* pR, const float2* pUR) {
    {
        M12 m = mkM(pUR[0], pUR[1], pUR[2], pUR[3]);
#pragma unroll
        for (int k = 0; k < 16; ++k)
            if (!(k & TB) && (k & CB))
                bfly(vr[k], vi[k], vr[k|TB], vi[k|TB], m);
    }
    {
        M12 m = mkM(pR[0], pR[1], pR[2], pR[3]);
#pragma unroll
        for (int k = 0; k < 16; ++k)
            if (!(k & TB) && !(k & CB))
                bfly(vr[k], vi[k], vr[k|TB], vi[k|TB], m);
    }
}

// MPS transfer factor for layer 0 (validated):
// h(0,*) = 1/sqrt2 ; h(1,0) = (-A,-B) ; h(1,1) = (B,-A)
__device__ __forceinline__ float2 hfun(int xb, int yb) {
    if (xb == 0) return make_float2(R2, 0.0f);
    return yb ? make_float2(CU_B, -CU_A)
              : make_float2(-CU_A, -CU_B);
}

__global__ void __launch_bounds__(128, 4)
qsim_kernel(const float* __restrict__ x,  const float* __restrict__ W1,
            const float* __restrict__ b1, const float* __restrict__ qw,
            const float* __restrict__ W2, const float* __restrict__ b2,
            float* __restrict__ out)
{
    __shared__ float2 Rm[50*4];    // R_{l,q}
    __shared__ float2 URm[40*4];   // U*R_{l,q}, l=0..3 (q=0 unused)

    const int tid = threadIdx.x;
    const int s   = tid >> 5;           // warp 0..3
    const int t   = tid & 31;
    const int c   = blockIdx.x >> 1;    // circuit
    const int b   = (blockIdx.x & 1) * 4 + s;  // batch row 0..7

    // R_{l,q} = RZ(w2) RY(w1) RZ(w0)
    if (tid < 50) {
        int l = tid / 10, q = tid - l * 10;
        const float* wp = qw + ((c*5 + l)*10 + q) * 3;
        float w0 = wp[0], w1v = wp[1], w2v = wp[2];
        float sy, cy; sincosf(0.5f * w1v,        &sy, &cy);
        float sp, cp; sincosf(0.5f * (w0 + w2v), &sp, &cp);
        float sm, cm; sincosf(0.5f * (w0 - w2v), &sm, &cm);
        Rm[tid*4+0] = make_float2( cy*cp, -cy*sp);
        Rm[tid*4+1] = make_float2(-sy*cm, -sy*sm);
        Rm[tid*4+2] = make_float2( sy*cm, -sy*sm);
        Rm[tid*4+3] = make_float2( cy*cp,  cy*sp);
    }
    __syncthreads();
    // UR_{l,q} = U * R_{l,q}
    if (tid < 40 && (tid % 10) != 0) {
        const float2 u00 = make_float2(CU_A,  CU_A);
        const float2 u01 = make_float2(CU_B, -CU_B);
        const float2 u10 = make_float2(CU_B,  CU_B);
        const float2 u11 = make_float2(-CU_A, CU_A);
        float2 r00 = Rm[tid*4+0], r01 = Rm[tid*4+1], r10 = Rm[tid*4+2], r11 = Rm[tid*4+3];
        URm[tid*4+0] = cadd(cmul(u00, r00), cmul(u01, r10));
        URm[tid*4+1] = cadd(cmul(u00, r01), cmul(u01, r11));
        URm[tid*4+2] = cadd(cmul(u10, r00), cmul(u11, r10));
        URm[tid*4+3] = cadd(cmul(u10, r01), cmul(u11, r11));
    }

    float hang = x[b*2+0]*W1[c*2+0] + x[b*2+1]*W1[c*2+1] + b1[c];
    float se, ce;
    sincosf(0.5f * hang, &se, &ce);

    u64 vr[16], vi[16];

    // ---- analytic layer 0 in pass-A layout ----
    // amp bits: [9:6]=k, [5:1]=t4..t0, [0]=packed lane
    // amp = E(b9) * h(b9,b8) h(b8,b7) ... h(b1,b0)
    const int t4 = (t >> 4) & 1;
    {
        float2 Tc = cmul(cmul(hfun(t4,(t>>3)&1), hfun((t>>3)&1,(t>>2)&1)),
                         cmul(hfun((t>>2)&1,(t>>1)&1), hfun((t>>1)&1, t&1)));
        float2 L0 = hfun(t&1, 0), L1 = hfun(t&1, 1);
        float2 T0 = cmul(Tc, L0), T1 = cmul(Tc, L1);
        u64 Tr = pack2(T0.x, T1.x), Ti = pack2(T0.y, T1.y);
        float E0 = (ce - se) * R2, E1 = (ce + se) * R2;
#pragma unroll
        for (int k = 0; k < 16; ++k) {
            int k3 = (k>>3)&1, k2 = (k>>2)&1, k1b = (k>>1)&1, k0 = k&1;
            float2 K = cmul(cmul(hfun(k3,k2), hfun(k2,k1b)),
                            cmul(hfun(k1b,k0), hfun(k0,t4)));
            float Ek = k3 ? E1 : E0;
            K.x *= Ek; K.y *= Ek;
            u64 kx = bc(K.x), ky = bc(K.y);
            vr[k] = ffma2(kx, Tr, fmul2(neg2(ky), Ti));
            vi[k] = ffma2(kx, Ti, fmul2(ky, Tr));
        }
    }

    __syncthreads();   // tables visible

    // ---- light-cone pruned layers 1..4, all in registers ----
    // layer l keeps: E'_l, then M(0,1)..M(4-l, 5-l); qubit q -> k bit (3-q)
#pragma unroll 1
    for (int l = 1; l <= 4; ++l) {
        const float2* Rp  = Rm  + (l-1)*40;
        const float2* URp = URm + (l-1)*40;

        // merged embedding: E' = emb_l * R_{l-1,0}, target k3
        {
            float2 r00 = Rp[0], r01 = Rp[1], r10 = Rp[2], r11 = Rp[3];
            float2 e00, e01, e10, e11;
            if ((l & 1) == 0) {  // RY (real)
                e00 = make_float2(ce*r00.x - se*r10.x, ce*r00.y - se*r10.y);
                e01 = make_float2(ce*r01.x - se*r11.x, ce*r01.y - se*r11.y);
                e10 = make_float2(se*r00.x + ce*r10.x, se*r00.y + ce*r10.y);
                e11 = make_float2(se*r01.x + ce*r11.x, se*r01.y + ce*r11.y);
            } else {             // RZ diag((ce,-se),(ce,se))
                float2 f0 = make_float2(ce, -se), f1 = make_float2(ce, se);
                e00 = cmul(f0, r00); e01 = cmul(f0, r01);
                e10 = cmul(f1, r10); e11 = cmul(f1, r11);
            }
            M12 me = mkM(e00, e01, e10, e11);
#pragma unroll
            for (int k = 0; k < 8; ++k)
                bfly(vr[k], vi[k], vr[k+8], vi[k+8], me);
        }
        merged_cu<8,4>(vr, vi, Rp + 1*4, URp + 1*4);                  // M(0,1)
        if (l <= 3) merged_cu<4,2>(vr, vi, Rp + 2*4, URp + 2*4);      // M(1,2)
        if (l <= 2) merged_cu<2,1>(vr, vi, Rp + 3*4, URp + 3*4);      // M(2,3)
        if (l == 1) {
            // M(3,4): control = k0, target = amp bit5 = lane bit4 (shfl 16)
            float2 rA = t4 ? Rp[4*4+2] : Rp[4*4+0];    // R_{0,4} row t4
            float2 rB = t4 ? Rp[4*4+3] : Rp[4*4+1];
            float2 uA = t4 ? URp[4*4+2] : URp[4*4+0];  // UR_{0,4} row t4
            float2 uB = t4 ? URp[4*4+3] : URp[4*4+1];
            u64 rAx=bc(rA.x), rAy=bc(rA.y), rBx=bc(rB.x), rBy=bc(rB.y);
            u64 uAx=bc(uA.x), uAy=bc(uA.y), uBx=bc(uB.x), uBy=bc(uB.y);
#pragma unroll
            for (int k = 0; k < 16; ++k) {
                u64 or_ = __shfl_xor_sync(0xffffffffu, vr[k], 16);
                u64 oi_ = __shfl_xor_sync(0xffffffffu, vi[k], 16);
                u64 a_r = t4 ? or_  : vr[k], a_i = t4 ? oi_  : vi[k];
                u64 b_r = t4 ? vr[k] : or_,  b_i = t4 ? vi[k] : oi_;
                u64 mAx = (k & 1) ? uAx : rAx, mAy = (k & 1) ? uAy : rAy;
                u64 mBx = (k & 1) ? uBx : rBx, mBy = (k & 1) ? uBy : rBy;
                u64 ti_ = ffma2(mAy, a_i, fmul2(mBy, b_i));
                vr[k] = ffma2(mAx, a_r, ffma2(mBx, b_r, neg2(ti_)));
                vi[k] = ffma2(mAy, a_r, ffma2(mAx, a_i, ffma2(mBy, b_r, fmul2(mBx, b_i))));
            }
        }
    }

    // ===== Measurement: <Z0>, trailing qubit-0 gate G = H * R40 * R40 =====
    float z;
    {
        float2 r00 = Rm[160], r01 = Rm[161], r10 = Rm[162], r11 = Rm[163];
        float2 s00 = cadd(cmul(r00,r00), cmul(r01,r10));
        float2 s01 = cadd(cmul(r00,r01), cmul(r01,r11));
        float2 s10 = cadd(cmul(r10,r00), cmul(r11,r10));
        float2 s11 = cadd(cmul(r10,r01), cmul(r11,r11));
        float2 g00 = make_float2(R2*(s00.x+s10.x), R2*(s00.y+s10.y));
        float2 g01 = make_float2(R2*(s01.x+s11.x), R2*(s01.y+s11.y));
        float2 g10 = make_float2(R2*(s00.x-s10.x), R2*(s00.y-s10.y));
        float2 g11 = make_float2(R2*(s01.x-s11.x), R2*(s01.y-s11.y));
        M12 gm = mkM(g00, g01, g10, g11);
        u64 acc = bc(0.0f);
#pragma unroll
        for (int k = 0; k < 8; ++k) {
            bfly(vr[k], vi[k], vr[k|8], vi[k|8], gm);
            acc = ffma2(vr[k],   vr[k],   acc);
            acc = ffma2(vi[k],   vi[k],   acc);
            acc = ffma2(neg2(vr[k|8]), vr[k|8], acc);
            acc = ffma2(neg2(vi[k|8]), vi[k|8], acc);
        }
        float2 av = unpk(acc);
        z = av.x + av.y;
#pragma unroll
        for (int off = 16; off > 0; off >>= 1) z += __shfl_down_sync(0xffffffffu, z, off);
    }
    if (t == 0) {
        atomicAdd(&g_acc[b*2 + 0], z * W2[c]);
        atomicAdd(&g_acc[b*2 + 1], z * W2[NC + c]);
    }
    __syncthreads();

    // last CTA finalizes: softmax + output + reset
    if (tid == 0) {
        __threadfence();
        unsigned int done = atomicAdd(&g_done, 1u);
        if (done == gridDim.x - 1) {
            __threadfence();
#pragma unroll
            for (int bb = 0; bb < 8; ++bb) {
                float l0 = g_acc[2*bb]   + b2[0];
                float l1 = g_acc[2*bb+1] + b2[1];
                float m  = fmaxf(l0, l1);
                float e0 = expf(l0 - m), e1 = expf(l1 - m);
                float inv = 1.0f / (e0 + e1);
                out[2*bb + 0] = e0 * inv;
                out[2*bb + 1] = e1 * inv;
                g_acc[2*bb]   = 0.0f;
                g_acc[2*bb+1] = 0.0f;
            }
            g_done = 0u;
            __threadfence();
        }
    }
}

extern "C" void kernel_launch(void* const* d_in, const int* in_sizes, int n_in,
                              void* d_out, int out_size) {
    const float* x  = (const float*)d_in[0];   // (8,2)
    const float* W1 = (const float*)d_in[1];   // (320,2)
    const float* b1 = (const float*)d_in[2];   // (320,)
    const float* qw = (const float*)d_in[3];   // (320,5,10,3)
    const float* W2 = (const float*)d_in[4];   // (2,320)
    const float* b2 = (const float*)d_in[5];   // (2,)
    float* out = (float*)d_out;                // (8,2)

    qsim_kernel<<<640, 128>>>(x, W1, b1, qw, W2, b2, out);
}

// round 9
// speedup vs baseline: 3.9404x; 1.4827x over previous
#include <cuda_runtime.h>

// Hybrid quantum model, v8: rank-2 sector decomposition of the light-cone
// pruned circuit. <Z0> = <phi0|O'|phi0> + <phi1|O'|phi1> where phi_b4 are
// 32-amp 5-qubit states (the two distinct sector shapes of the layer-0 MPS;
// all sector weights |G|^2 sum to 1 exactly since |h|^2 = 1/2).
// Warp = one (circuit,batch); 32 amps in lanes; phi0/phi1 in f32x2 lanes.
// All gates are shfl-xor half-butterflies. Single launch, last-CTA finalize.

#define NC   320

typedef unsigned long long u64;

__device__ float g_acc[16];          // partial logits [batch][2]
__device__ unsigned int g_done;      // CTA completion counter

#define CU_A (-0.2705980500730985f)
#define CU_B ( 0.6532814824381883f)
#define R2   ( 0.7071067811865476f)

// ---------------- packed f32x2 helpers ----------------
__device__ __forceinline__ u64 pack2(float x, float y) {
    u64 u; asm("mov.b64 %0,{%1,%2};" : "=l"(u) : "f"(x), "f"(y)); return u;
}
__device__ __forceinline__ float2 unpk(u64 u) {
    float2 v; asm("mov.b64 {%0,%1},%2;" : "=f"(v.x), "=f"(v.y) : "l"(u)); return v;
}
__device__ __forceinline__ u64 bc(float x) { return pack2(x, x); }
__device__ __forceinline__ u64 ffma2(u64 a, u64 b, u64 c) {
    u64 d; asm("fma.rn.f32x2 %0,%1,%2,%3;" : "=l"(d) : "l"(a), "l"(b), "l"(c)); return d;
}
__device__ __forceinline__ u64 fmul2(u64 a, u64 b) {
    u64 d; asm("mul.rn.f32x2 %0,%1,%2;" : "=l"(d) : "l"(a), "l"(b)); return d;
}
__device__ __forceinline__ u64 fadd2(u64 a, u64 b) {
    u64 d; asm("add.rn.f32x2 %0,%1,%2;" : "=l"(d) : "l"(a), "l"(b)); return d;
}
__device__ __forceinline__ u64 neg2(u64 a) { return a ^ 0x8000000080000000ull; }

__device__ __forceinline__ float2 cmul(float2 a, float2 b) {
    return make_float2(a.x*b.x - a.y*b.y, a.x*b.y + a.y*b.x);
}
__device__ __forceinline__ float2 cadd(float2 a, float2 b) {
    return make_float2(a.x + b.x, a.y + b.y);
}

// MPS transfer factor (validated): h(0,*)=1/sqrt2; h(1,0)=(-A,-B); h(1,1)=(B,-A)
__device__ __forceinline__ float2 hfun(int xb, int yb) {
    if (xb == 0) return make_float2(R2, 0.0f);
    return yb ? make_float2(CU_B, -CU_A)
              : make_float2(-CU_A, -CU_B);
}

// half-butterfly on lane-resident amp: target bit = mask; row entries (p,q).
// new = p*amp(tgt=0) + q*amp(tgt=1)
__device__ __forceinline__ void gate(u64& vr, u64& vi, int t, int mask,
                                     float2 p, float2 q) {
    u64 or_ = __shfl_xor_sync(0xffffffffu, vr, mask);
    u64 oi_ = __shfl_xor_sync(0xffffffffu, vi, mask);
    bool tb = (t & mask) != 0;
    u64 ar = tb ? or_ : vr,  ai = tb ? oi_ : vi;
    u64 br = tb ? vr  : or_, bi = tb ? vi  : oi_;
    u64 px = bc(p.x), py = bc(p.y), qx = bc(q.x), qy = bc(q.y);
    u64 ti = ffma2(py, ai, fmul2(qy, bi));
    vr = ffma2(px, ar, ffma2(qx, br, neg2(ti)));
    vi = ffma2(py, ar, ffma2(px, ai, ffma2(qy, br, fmul2(qx, bi))));
}

__global__ void __launch_bounds__(128, 4)
qsim_kernel(const float* __restrict__ x,  const float* __restrict__ W1,
            const float* __restrict__ b1, const float* __restrict__ qw,
            const float* __restrict__ W2, const float* __restrict__ b2,
            float* __restrict__ out)
{
    __shared__ float2 Rm[50*4];    // R_{l,q}
    __shared__ float2 URm[40*4];   // U*R_{l,q}, l=0..3 (q=0 unused)

    const int tid = threadIdx.x;
    const int s   = tid >> 5;           // warp 0..3
    const int t   = tid & 31;
    const int c   = blockIdx.x >> 1;    // circuit
    const int b   = (blockIdx.x & 1) * 4 + s;  // batch row 0..7

    // R_{l,q} = RZ(w2) RY(w1) RZ(w0)
    if (tid < 50) {
        int l = tid / 10, q = tid - l * 10;
        const float* wp = qw + ((c*5 + l)*10 + q) * 3;
        float w0 = wp[0], w1v = wp[1], w2v = wp[2];
        float sy, cy; sincosf(0.5f * w1v,        &sy, &cy);
        float sp, cp; sincosf(0.5f * (w0 + w2v), &sp, &cp);
        float sm, cm; sincosf(0.5f * (w0 - w2v), &sm, &cm);
        Rm[tid*4+0] = make_float2( cy*cp, -cy*sp);
        Rm[tid*4+1] = make_float2(-sy*cm, -sy*sm);
        Rm[tid*4+2] = make_float2( sy*cm, -sy*sm);
        Rm[tid*4+3] = make_float2( cy*cp,  cy*sp);
    }
    __syncthreads();
    // UR_{l,q} = U * R_{l,q}
    if (tid < 40 && (tid % 10) != 0) {
        const float2 u00 = make_float2(CU_A,  CU_A);
        const float2 u01 = make_float2(CU_B, -CU_B);
        const float2 u10 = make_float2(CU_B,  CU_B);
        const float2 u11 = make_float2(-CU_A, CU_A);
        float2 r00 = Rm[tid*4+0], r01 = Rm[tid*4+1], r10 = Rm[tid*4+2], r11 = Rm[tid*4+3];
        URm[tid*4+0] = cadd(cmul(u00, r00), cmul(u01, r10));
        URm[tid*4+1] = cadd(cmul(u00, r01), cmul(u01, r11));
        URm[tid*4+2] = cadd(cmul(u10, r00), cmul(u11, r10));
        URm[tid*4+3] = cadd(cmul(u10, r01), cmul(u11, r11));
    }

    float hang = x[b*2+0]*W1[c*2+0] + x[b*2+1]*W1[c*2+1] + b1[c];
    float se, ce;
    sincosf(0.5f * hang, &se, &ce);

    // state bits: qubit q -> lane bit (4-q); a4=t4..a0=t0; packed lane = b4
    const int t4 = (t >> 4) & 1;
    const int t3 = (t >> 3) & 1, t2 = (t >> 2) & 1, t1b = (t >> 1) & 1, t0 = t & 1;

    // ---- init: phi_b4(a) = E(a4) * h(a4,a3)h(a3,a2)h(a2,a1)h(a1,a0) * h(a0,b4)
    u64 vr, vi;
    {
        float2 P = cmul(cmul(hfun(t4,t3), hfun(t3,t2)),
                        cmul(hfun(t2,t1b), hfun(t1b,t0)));
        float2 T0 = cmul(P, hfun(t0, 0));
        float2 T1 = cmul(P, hfun(t0, 1));
        float E = t4 ? (ce + se) * R2 : (ce - se) * R2;
        vr = pack2(E * T0.x, E * T1.x);
        vi = pack2(E * T0.y, E * T1.y);
    }

    __syncthreads();   // tables visible

    // ---- light-cone pruned layers 1..4 ----
#pragma unroll 1
    for (int l = 1; l <= 4; ++l) {
        const float2* Rp  = Rm  + (l-1)*40;
        const float2* URp = URm + (l-1)*40;

        // merged embedding E' = emb_l * R_{l-1,0} on q0 (mask 16)
        {
            float2 r00 = Rp[0], r01 = Rp[1], r10 = Rp[2], r11 = Rp[3];
            float2 e00, e01, e10, e11;
            if ((l & 1) == 0) {  // RY (real)
                e00 = make_float2(ce*r00.x - se*r10.x, ce*r00.y - se*r10.y);
                e01 = make_float2(ce*r01.x - se*r11.x, ce*r01.y - se*r11.y);
                e10 = make_float2(se*r00.x + ce*r10.x, se*r00.y + ce*r10.y);
                e11 = make_float2(se*r01.x + ce*r11.x, se*r01.y + ce*r11.y);
            } else {             // RZ diag((ce,-se),(ce,se))
                float2 f0 = make_float2(ce, -se), f1 = make_float2(ce, se);
                e00 = cmul(f0, r00); e01 = cmul(f0, r01);
                e10 = cmul(f1, r10); e11 = cmul(f1, r11);
            }
            gate(vr, vi, t, 16, t4 ? e10 : e00, t4 ? e11 : e01);
        }
        // M(0,1): ctrl bit4, tgt bit3
        {
            const float2* base = ((t & 16) ? URp : Rp) + 1*4;
            int r = (t & 8) ? 2 : 0;
            gate(vr, vi, t, 8, base[r], base[r+1]);
        }
        if (l <= 3) {  // M(1,2): ctrl bit3, tgt bit2
            const float2* base = ((t & 8) ? URp : Rp) + 2*4;
            int r = (t & 4) ? 2 : 0;
            gate(vr, vi, t, 4, base[r], base[r+1]);
        }
        if (l <= 2) {  // M(2,3): ctrl bit2, tgt bit1
            const float2* base = ((t & 4) ? URp : Rp) + 3*4;
            int r = (t & 2) ? 2 : 0;
            gate(vr, vi, t, 2, base[r], base[r+1]);
        }
        if (l == 1) {  // M(3,4): ctrl bit1, tgt bit0
            const float2* base = ((t & 2) ? URp : Rp) + 4*4;
            int r = (t & 1) ? 2 : 0;
            gate(vr, vi, t, 1, base[r], base[r+1]);
        }
    }

    // ===== Measurement: <Z0>, trailing qubit-0 gate G = H * R40 * R40 =====
    {
        float2 r00 = Rm[160], r01 = Rm[161], r10 = Rm[162], r11 = Rm[163];
        float2 s00 = cadd(cmul(r00,r00), cmul(r01,r10));
        float2 s01 = cadd(cmul(r00,r01), cmul(r01,r11));
        float2 s10 = cadd(cmul(r10,r00), cmul(r11,r10));
        float2 s11 = cadd(cmul(r10,r01), cmul(r11,r11));
        float2 g00 = make_float2(R2*(s00.x+s10.x), R2*(s00.y+s10.y));
        float2 g01 = make_float2(R2*(s01.x+s11.x), R2*(s01.y+s11.y));
        float2 g10 = make_float2(R2*(s00.x-s10.x), R2*(s00.y-s10.y));
        float2 g11 = make_float2(R2*(s01.x-s11.x), R2*(s01.y-s11.y));
        gate(vr, vi, t, 16, t4 ? g10 : g00, t4 ? g11 : g01);

        u64 sq = ffma2(vr, vr, fmul2(vi, vi));
        if (t4) sq = neg2(sq);
#pragma unroll
        for (int off = 16; off > 0; off >>= 1)
            sq = fadd2(sq, __shfl_down_sync(0xffffffffu, sq, off));
        if (t == 0) {
            float2 zv = unpk(sq);
            float z = zv.x + zv.y;   // phi0 + phi1 contributions
            atomicAdd(&g_acc[b*2 + 0], z * W2[c]);
            atomicAdd(&g_acc[b*2 + 1], z * W2[NC + c]);
        }
    }
    __syncthreads();

    // last CTA finalizes: softmax + output + reset
    if (tid == 0) {
        __threadfence();
        unsigned int done = atomicAdd(&g_done, 1u);
        if (done == gridDim.x - 1) {
            __threadfence();
#pragma unroll
            for (int bb = 0; bb < 8; ++bb) {
                float l0 = g_acc[2*bb]   + b2[0];
                float l1 = g_acc[2*bb+1] + b2[1];
                float m  = fmaxf(l0, l1);
                float e0 = expf(l0 - m), e1 = expf(l1 - m);
                float inv = 1.0f / (e0 + e1);
                out[2*bb + 0] = e0 * inv;
                out[2*bb + 1] = e1 * inv;
                g_acc[2*bb]   = 0.0f;
                g_acc[2*bb+1] = 0.0f;
            }
            g_done = 0u;
            __threadfence();
        }
    }
}

extern "C" void kernel_launch(void* const* d_in, const int* in_sizes, int n_in,
                              void* d_out, int out_size) {
    const float* x  = (const float*)d_in[0];   // (8,2)
    const float* W1 = (const float*)d_in[1];   // (320,2)
    const float* b1 = (const float*)d_in[2];   // (320,)
    const float* qw = (const float*)d_in[3];   // (320,5,10,3)
    const float* W2 = (const float*)d_in[4];   // (2,320)
    const float* b2 = (const float*)d_in[5];   // (2,)
    float* out = (float*)d_out;                // (8,2)

    qsim_kernel<<<640, 128>>>(x, W1, b1, qw, W2, b2, out);
}

// round 10
// speedup vs baseline: 5.1097x; 1.2968x over previous
#include <cuda_runtime.h>

// Hybrid quantum model, v9: rank-2 sector sim (v8, validated) with
// - 1 CTA per circuit (grid 320, block 256): tables computed once
// - light-cone-pruned tables (15 matrices, not 50), __sincosf fast path
// - bucketed atomic accumulation (8 buckets, 8x less per-address contention)
// - fully unrolled layer loop

#define NC   320

typedef unsigned long long u64;

__device__ float g_accB[8*16];       // [bucket][batch*2+j] partial logits
__device__ unsigned int g_done;      // CTA completion counter

#define CU_A (-0.2705980500730985f)
#define CU_B ( 0.6532814824381883f)
#define R2   ( 0.7071067811865476f)

// ---------------- packed f32x2 helpers ----------------
__device__ __forceinline__ u64 pack2(float x, float y) {
    u64 u; asm("mov.b64 %0,{%1,%2};" : "=l"(u) : "f"(x), "f"(y)); return u;
}
__device__ __forceinline__ float2 unpk(u64 u) {
    float2 v; asm("mov.b64 {%0,%1},%2;" : "=f"(v.x), "=f"(v.y) : "l"(u)); return v;
}
__device__ __forceinline__ u64 bc(float x) { return pack2(x, x); }
__device__ __forceinline__ u64 ffma2(u64 a, u64 b, u64 c) {
    u64 d; asm("fma.rn.f32x2 %0,%1,%2,%3;" : "=l"(d) : "l"(a), "l"(b), "l"(c)); return d;
}
__device__ __forceinline__ u64 fmul2(u64 a, u64 b) {
    u64 d; asm("mul.rn.f32x2 %0,%1,%2;" : "=l"(d) : "l"(a), "l"(b)); return d;
}
__device__ __forceinline__ u64 fadd2(u64 a, u64 b) {
    u64 d; asm("add.rn.f32x2 %0,%1,%2;" : "=l"(d) : "l"(a), "l"(b)); return d;
}
__device__ __forceinline__ u64 neg2(u64 a) { return a ^ 0x8000000080000000ull; }

__device__ __forceinline__ float2 cmul(float2 a, float2 b) {
    return make_float2(a.x*b.x - a.y*b.y, a.x*b.y + a.y*b.x);
}
__device__ __forceinline__ float2 cadd(float2 a, float2 b) {
    return make_float2(a.x + b.x, a.y + b.y);
}

// MPS transfer factor (validated): h(0,*)=1/sqrt2; h(1,0)=(-A,-B); h(1,1)=(B,-A)
__device__ __forceinline__ float2 hfun(int xb, int yb) {
    if (xb == 0) return make_float2(R2, 0.0f);
    return yb ? make_float2(CU_B, -CU_A)
              : make_float2(-CU_A, -CU_B);
}

// half-butterfly on lane-resident amp: target bit = mask; row entries (p,q).
__device__ __forceinline__ void gate(u64& vr, u64& vi, int t, int mask,
                                     float2 p, float2 q) {
    u64 or_ = __shfl_xor_sync(0xffffffffu, vr, mask);
    u64 oi_ = __shfl_xor_sync(0xffffffffu, vi, mask);
    bool tb = (t & mask) != 0;
    u64 ar = tb ? or_ : vr,  ai = tb ? oi_ : vi;
    u64 br = tb ? vr  : or_, bi = tb ? vi  : oi_;
    u64 px = bc(p.x), py = bc(p.y), qx = bc(q.x), qy = bc(q.y);
    u64 ti = ffma2(py, ai, fmul2(qy, bi));
    vr = ffma2(px, ar, ffma2(qx, br, neg2(ti)));
    vi = ffma2(py, ar, ffma2(px, ai, ffma2(qy, br, fmul2(qx, bi))));
}

// light-cone (l,q) pairs needing R/UR tables (q>=1): index base per l
__device__ __constant__ int LQ_L[10] = {0,0,0,0,1,1,1,2,2,3};
__device__ __constant__ int LQ_Q[10] = {1,2,3,4,1,2,3,1,2,1};
// pair-table base index for layer l-1 in main loop: {0,4,7,9}

__global__ void __launch_bounds__(256, 4)
qsim_kernel(const float* __restrict__ x,  const float* __restrict__ W1,
            const float* __restrict__ b1, const float* __restrict__ qw,
            const float* __restrict__ W2, const float* __restrict__ b2,
            float* __restrict__ out)
{
    __shared__ float2 R0f[5*4];    // R_{l,0}, l=0..4
    __shared__ float2 Rq[10*4];    // cone R_{l,q}
    __shared__ float2 URq[10*4];   // cone U*R_{l,q}
    __shared__ float  zsh[8];

    const int tid = threadIdx.x;
    const int s   = tid >> 5;      // warp = batch row 0..7
    const int t   = tid & 31;
    const int c   = blockIdx.x;    // circuit

    // ---- table prep: only the 15 light-cone matrices ----
    if (tid < 15) {
        int l, q;
        if (tid < 5) { l = tid; q = 0; }
        else         { l = LQ_L[tid-5]; q = LQ_Q[tid-5]; }
        const float* wp = qw + ((c*5 + l)*10 + q) * 3;
        float w0 = wp[0], w1v = wp[1], w2v = wp[2];
        float sy, cy; __sincosf(0.5f * w1v,        &sy, &cy);
        float sp, cp; __sincosf(0.5f * (w0 + w2v), &sp, &cp);
        float sm, cm; __sincosf(0.5f * (w0 - w2v), &sm, &cm);
        float2 r00 = make_float2( cy*cp, -cy*sp);
        float2 r01 = make_float2(-sy*cm, -sy*sm);
        float2 r10 = make_float2( sy*cm, -sy*sm);
        float2 r11 = make_float2( cy*cp,  cy*sp);
        if (tid < 5) {
            R0f[tid*4+0]=r00; R0f[tid*4+1]=r01; R0f[tid*4+2]=r10; R0f[tid*4+3]=r11;
        } else {
            int pi = tid - 5;
            Rq[pi*4+0]=r00; Rq[pi*4+1]=r01; Rq[pi*4+2]=r10; Rq[pi*4+3]=r11;
        }
    }
    __syncthreads();
    if (tid < 10) {
        const float2 u00 = make_float2(CU_A,  CU_A);
        const float2 u01 = make_float2(CU_B, -CU_B);
        const float2 u10 = make_float2(CU_B,  CU_B);
        const float2 u11 = make_float2(-CU_A, CU_A);
        float2 r00 = Rq[tid*4+0], r01 = Rq[tid*4+1], r10 = Rq[tid*4+2], r11 = Rq[tid*4+3];
        URq[tid*4+0] = cadd(cmul(u00, r00), cmul(u01, r10));
        URq[tid*4+1] = cadd(cmul(u00, r01), cmul(u01, r11));
        URq[tid*4+2] = cadd(cmul(u10, r00), cmul(u11, r10));
        URq[tid*4+3] = cadd(cmul(u10, r01), cmul(u11, r11));
    }

    float hang = x[s*2+0]*W1[c*2+0] + x[s*2+1]*W1[c*2+1] + b1[c];
    float se, ce;
    __sincosf(0.5f * hang, &se, &ce);

    // state bits: qubit q -> lane bit (4-q); packed lane = b4 (sector shape)
    const int t4 = (t >> 4) & 1;
    const int t3 = (t >> 3) & 1, t2 = (t >> 2) & 1, t1b = (t >> 1) & 1, t0 = t & 1;

    // ---- init: phi_b4(a) = E(a4) * h(a4,a3)...h(a1,a0) * h(a0,b4) ----
    u64 vr, vi;
    {
        float2 P = cmul(cmul(hfun(t4,t3), hfun(t3,t2)),
                        cmul(hfun(t2,t1b), hfun(t1b,t0)));
        float2 T0 = cmul(P, hfun(t0, 0));
        float2 T1 = cmul(P, hfun(t0, 1));
        float E = t4 ? (ce + se) * R2 : (ce - se) * R2;
        vr = pack2(E * T0.x, E * T1.x);
        vi = pack2(E * T0.y, E * T1.y);
    }

    __syncthreads();   // tables visible

    // ---- light-cone pruned layers 1..4 (fully unrolled) ----
    const int PB[4] = {0, 4, 7, 9};   // pair-table base for layer l-1
#pragma unroll
    for (int l = 1; l <= 4; ++l) {
        const int B = PB[l-1];

        // merged embedding E' = emb_l * R_{l-1,0} on q0 (mask 16)
        {
            const float2* Rp0 = R0f + (l-1)*4;
            float2 r00 = Rp0[0], r01 = Rp0[1], r10 = Rp0[2], r11 = Rp0[3];
            float2 e00, e01, e10, e11;
            if ((l & 1) == 0) {  // RY (real)
                e00 = make_float2(ce*r00.x - se*r10.x, ce*r00.y - se*r10.y);
                e01 = make_float2(ce*r01.x - se*r11.x, ce*r01.y - se*r11.y);
                e10 = make_float2(se*r00.x + ce*r10.x, se*r00.y + ce*r10.y);
                e11 = make_float2(se*r01.x + ce*r11.x, se*r01.y + ce*r11.y);
            } else {             // RZ diag((ce,-se),(ce,se))
                float2 f0 = make_float2(ce, -se), f1 = make_float2(ce, se);
                e00 = cmul(f0, r00); e01 = cmul(f0, r01);
                e10 = cmul(f1, r10); e11 = cmul(f1, r11);
            }
            gate(vr, vi, t, 16, t4 ? e10 : e00, t4 ? e11 : e01);
        }
        // M(0,1): ctrl bit4, tgt bit3
        {
            const float2* base = ((t & 16) ? URq : Rq) + (B+0)*4;
            int r = (t & 8) ? 2 : 0;
            gate(vr, vi, t, 8, base[r], base[r+1]);
        }
        if (l <= 3) {  // M(1,2): ctrl bit3, tgt bit2
            const float2* base = ((t & 8) ? URq : Rq) + (B+1)*4;
            int r = (t & 4) ? 2 : 0;
            gate(vr, vi, t, 4, base[r], base[r+1]);
        }
        if (l <= 2) {  // M(2,3): ctrl bit2, tgt bit1
            const float2* base = ((t & 4) ? URq : Rq) + (B+2)*4;
            int r = (t & 2) ? 2 : 0;
            gate(vr, vi, t, 2, base[r], base[r+1]);
        }
        if (l == 1) {  // M(3,4): ctrl bit1, tgt bit0
            const float2* base = ((t & 2) ? URq : Rq) + (B+3)*4;
            int r = (t & 1) ? 2 : 0;
            gate(vr, vi, t, 1, base[r], base[r+1]);
        }
    }

    // ===== Measurement: <Z0>, trailing qubit-0 gate G = H * R40 * R40 =====
    {
        float2 r00 = R0f[16], r01 = R0f[17], r10 = R0f[18], r11 = R0f[19];
        float2 s00 = cadd(cmul(r00,r00), cmul(r01,r10));
        float2 s01 = cadd(cmul(r00,r01), cmul(r01,r11));
        float2 s10 = cadd(cmul(r10,r00), cmul(r11,r10));
        float2 s11 = cadd(cmul(r10,r01), cmul(r11,r11));
        float2 g00 = make_float2(R2*(s00.x+s10.x), R2*(s00.y+s10.y));
        float2 g01 = make_float2(R2*(s01.x+s11.x), R2*(s01.y+s11.y));
        float2 g10 = make_float2(R2*(s00.x-s10.x), R2*(s00.y-s10.y));
        float2 g11 = make_float2(R2*(s01.x-s11.x), R2*(s01.y-s11.y));
        gate(vr, vi, t, 16, t4 ? g10 : g00, t4 ? g11 : g01);

        u64 sq = ffma2(vr, vr, fmul2(vi, vi));
        if (t4) sq = neg2(sq);
#pragma unroll
        for (int off = 16; off > 0; off >>= 1)
            sq = fadd2(sq, __shfl_down_sync(0xffffffffu, sq, off));
        if (t == 0) {
            float2 zv = unpk(sq);
            zsh[s] = zv.x + zv.y;   // phi0 + phi1 contributions
        }
    }
    __syncthreads();

    // bucketed accumulation: 16 atomics per CTA, 8 buckets
    if (tid < 8) {
        int bucket = blockIdx.x & 7;
        float zz = zsh[tid];
        atomicAdd(&g_accB[bucket*16 + tid*2 + 0], zz * W2[c]);
        atomicAdd(&g_accB[bucket*16 + tid*2 + 1], zz * W2[NC + c]);
    }
    __syncthreads();

    // last CTA finalizes: sum buckets, softmax, output, reset
    if (tid == 0) {
        __threadfence();
        unsigned int done = atomicAdd(&g_done, 1u);
        if (done == gridDim.x - 1) {
            __threadfence();
#pragma unroll
            for (int bb = 0; bb < 8; ++bb) {
                float l0 = b2[0], l1 = b2[1];
#pragma unroll
                for (int k = 0; k < 8; ++k) {
                    l0 += g_accB[k*16 + 2*bb + 0];
                    l1 += g_accB[k*16 + 2*bb + 1];
                }
                float m  = fmaxf(l0, l1);
                float e0 = expf(l0 - m), e1 = expf(l1 - m);
                float inv = 1.0f / (e0 + e1);
                out[2*bb + 0] = e0 * inv;
                out[2*bb + 1] = e1 * inv;
            }
#pragma unroll
            for (int i = 0; i < 128; ++i) g_accB[i] = 0.0f;
            g_done = 0u;
            __threadfence();
        }
    }
}

extern "C" void kernel_launch(void* const* d_in, const int* in_sizes, int n_in,
                              void* d_out, int out_size) {
    const float* x  = (const float*)d_in[0];   // (8,2)
    const float* W1 = (const float*)d_in[1];   // (320,2)
    const float* b1 = (const float*)d_in[2];   // (320,)
    const float* qw = (const float*)d_in[3];   // (320,5,10,3)
    const float* W2 = (const float*)d_in[4];   // (2,320)
    const float* b2 = (const float*)d_in[5];   // (2,)
    float* out = (float*)d_out;                // (8,2)

    qsim_kernel<<<320, 256>>>(x, W1, b1, qw, W2, b2, out);
}

// round 11
// speedup vs baseline: 5.3221x; 1.0416x over previous
#include <cuda_runtime.h>

// Hybrid quantum model, v10: rank-2 sector sim with q0 in the f32x2 packed
// dimension (q0 gates become lane-internal scalar butterflies -> no shfl),
// sector b4 in lane bit4 (untouched by gates). Light-cone tables (15
// matrices), bucketed atomics from warp leaders, 16-lane parallel finalize.

#define NC   320

typedef unsigned long long u64;

__device__ float g_accB[8*16];       // [bucket][batch*2+j] partial logits
__device__ unsigned int g_done;      // CTA completion counter

#define CU_A (-0.2705980500730985f)
#define CU_B ( 0.6532814824381883f)
#define R2   ( 0.7071067811865476f)

// ---------------- packed f32x2 helpers ----------------
__device__ __forceinline__ u64 pack2(float x, float y) {
    u64 u; asm("mov.b64 %0,{%1,%2};" : "=l"(u) : "f"(x), "f"(y)); return u;
}
__device__ __forceinline__ float2 unpk(u64 u) {
    float2 v; asm("mov.b64 {%0,%1},%2;" : "=f"(v.x), "=f"(v.y) : "l"(u)); return v;
}
__device__ __forceinline__ u64 bc(float x) { return pack2(x, x); }
__device__ __forceinline__ u64 ffma2(u64 a, u64 b, u64 c) {
    u64 d; asm("fma.rn.f32x2 %0,%1,%2,%3;" : "=l"(d) : "l"(a), "l"(b), "l"(c)); return d;
}
__device__ __forceinline__ u64 fmul2(u64 a, u64 b) {
    u64 d; asm("mul.rn.f32x2 %0,%1,%2;" : "=l"(d) : "l"(a), "l"(b)); return d;
}
__device__ __forceinline__ u64 neg2(u64 a) { return a ^ 0x8000000080000000ull; }

__device__ __forceinline__ float2 cmul(float2 a, float2 b) {
    return make_float2(a.x*b.x - a.y*b.y, a.x*b.y + a.y*b.x);
}
__device__ __forceinline__ float2 cadd(float2 a, float2 b) {
    return make_float2(a.x + b.x, a.y + b.y);
}

// MPS transfer factor (validated): h(0,*)=1/sqrt2; h(1,0)=(-A,-B); h(1,1)=(B,-A)
__device__ __forceinline__ float2 hfun(int xb, int yb) {
    if (xb == 0) return make_float2(R2, 0.0f);
    return yb ? make_float2(CU_B, -CU_A)
              : make_float2(-CU_A, -CU_B);
}

// shfl half-butterfly, coefficients prebuilt as u64 (may differ per f32x2 lane)
__device__ __forceinline__ void gate_u64(u64& vr, u64& vi, int t, int mask,
                                         u64 px, u64 py, u64 qx, u64 qy) {
    u64 or_ = __shfl_xor_sync(0xffffffffu, vr, mask);
    u64 oi_ = __shfl_xor_sync(0xffffffffu, vi, mask);
    bool tb = (t & mask) != 0;
    u64 ar = tb ? or_ : vr,  ai = tb ? oi_ : vi;
    u64 br = tb ? vr  : or_, bi = tb ? vi  : oi_;
    u64 ti = ffma2(py, ai, fmul2(qy, bi));
    vr = ffma2(px, ar, ffma2(qx, br, neg2(ti)));
    vi = ffma2(py, ar, ffma2(px, ai, ffma2(qy, br, fmul2(qx, bi))));
}

// lane-internal complex 2x2 on the f32x2 components (q0 gate; proven in v4)
__device__ __forceinline__ void lane_bfly(u64& r, u64& i,
        float x00, float y00, float x01, float y01,
        float x10, float y10, float x11, float y11) {
    float2 rr = unpk(r), ii = unpk(i);
    float ax = rr.x, bx = rr.y, ay = ii.x, by = ii.y;
    float nax = x00*ax - y00*ay + x01*bx - y01*by;
    float nay = y00*ax + x00*ay + y01*bx + x01*by;
    float nbx = x10*ax - y10*ay + x11*bx - y11*by;
    float nby = y10*ax + x10*ay + y11*bx + x11*by;
    r = pack2(nax, nbx); i = pack2(nay, nby);
}

// light-cone (l,q) pairs needing R/UR tables (q>=1)
__device__ __constant__ int LQ_L[10] = {0,0,0,0,1,1,1,2,2,3};
__device__ __constant__ int LQ_Q[10] = {1,2,3,4,1,2,3,1,2,1};

__global__ void __launch_bounds__(256, 2)
qsim_kernel(const float* __restrict__ x,  const float* __restrict__ W1,
            const float* __restrict__ b1, const float* __restrict__ qw,
            const float* __restrict__ W2, const float* __restrict__ b2,
            float* __restrict__ out)
{
    __shared__ float2 R0f[5*4];    // R_{l,0}, l=0..4
    __shared__ float2 Rq[10*4];    // cone R_{l,q}
    __shared__ float2 URq[10*4];   // cone U*R_{l,q}
    __shared__ unsigned int lastf;

    const int tid = threadIdx.x;
    const int s   = tid >> 5;      // warp = batch row 0..7
    const int t   = tid & 31;
    const int c   = blockIdx.x;    // circuit

    // ---- table prep: only the 15 light-cone matrices ----
    if (tid < 15) {
        int l, q;
        if (tid < 5) { l = tid; q = 0; }
        else         { l = LQ_L[tid-5]; q = LQ_Q[tid-5]; }
        const float* wp = qw + ((c*5 + l)*10 + q) * 3;
        float w0 = wp[0], w1v = wp[1], w2v = wp[2];
        float sy, cy; __sincosf(0.5f * w1v,        &sy, &cy);
        float sp, cp; __sincosf(0.5f * (w0 + w2v), &sp, &cp);
        float sm, cm; __sincosf(0.5f * (w0 - w2v), &sm, &cm);
        float2 r00 = make_float2( cy*cp, -cy*sp);
        float2 r01 = make_float2(-sy*cm, -sy*sm);
        float2 r10 = make_float2( sy*cm, -sy*sm);
        float2 r11 = make_float2( cy*cp,  cy*sp);
        if (tid < 5) {
            R0f[tid*4+0]=r00; R0f[tid*4+1]=r01; R0f[tid*4+2]=r10; R0f[tid*4+3]=r11;
        } else {
            int pi = tid - 5;
            Rq[pi*4+0]=r00; Rq[pi*4+1]=r01; Rq[pi*4+2]=r10; Rq[pi*4+3]=r11;
        }
    }
    __syncthreads();
    if (tid < 10) {
        const float2 u00 = make_float2(CU_A,  CU_A);
        const float2 u01 = make_float2(CU_B, -CU_B);
        const float2 u10 = make_float2(CU_B,  CU_B);
        const float2 u11 = make_float2(-CU_A, CU_A);
        float2 r00 = Rq[tid*4+0], r01 = Rq[tid*4+1], r10 = Rq[tid*4+2], r11 = Rq[tid*4+3];
        URq[tid*4+0] = cadd(cmul(u00, r00), cmul(u01, r10));
        URq[tid*4+1] = cadd(cmul(u00, r01), cmul(u01, r11));
        URq[tid*4+2] = cadd(cmul(u10, r00), cmul(u11, r10));
        URq[tid*4+3] = cadd(cmul(u10, r01), cmul(u11, r11));
    }

    float hang = x[s*2+0]*W1[c*2+0] + x[s*2+1]*W1[c*2+1] + b1[c];
    float se, ce;
    __sincosf(0.5f * hang, &se, &ce);

    // layout: packed f32x2 = a4 (q0) in {0,1}; lane bit4 = sector b4;
    //         lane bits 3..0 = a3..a0 (qubits 1..4)
    const int t4 = (t >> 4) & 1;
    const int t3 = (t >> 3) & 1, t2 = (t >> 2) & 1, t1b = (t >> 1) & 1, t0 = t & 1;

    // ---- init: amp = E(a4) h(a4,a3) [h(a3,a2)h(a2,a1)h(a1,a0)h(a0,b4)] ----
    u64 vr, vi;
    {
        float2 C = cmul(cmul(hfun(t3,t2), hfun(t2,t1b)),
                        cmul(hfun(t1b,t0), hfun(t0,t4)));
        float E0 = (ce - se) * R2, E1 = (ce + se) * R2;
        float2 D = cmul(hfun(1, t3), C);       // comp1 chain head
        float s0 = E0 * R2;                    // comp0: h(0,a3) = (R2,0)
        vr = pack2(s0 * C.x, E1 * D.x);
        vi = pack2(s0 * C.y, E1 * D.y);
    }

    __syncthreads();   // tables visible

    // ---- light-cone pruned layers 1..4 (fully unrolled) ----
    const int PB[4] = {0, 4, 7, 9};
#pragma unroll
    for (int l = 1; l <= 4; ++l) {
        const int B = PB[l-1];

        // merged embedding E' = emb_l * R_{l-1,0} on q0: lane-internal
        {
            const float2* Rp0 = R0f + (l-1)*4;
            float2 r00 = Rp0[0], r01 = Rp0[1], r10 = Rp0[2], r11 = Rp0[3];
            float2 e00, e01, e10, e11;
            if ((l & 1) == 0) {  // RY (real)
                e00 = make_float2(ce*r00.x - se*r10.x, ce*r00.y - se*r10.y);
                e01 = make_float2(ce*r01.x - se*r11.x, ce*r01.y - se*r11.y);
                e10 = make_float2(se*r00.x + ce*r10.x, se*r00.y + ce*r10.y);
                e11 = make_float2(se*r01.x + ce*r11.x, se*r01.y + ce*r11.y);
            } else {             // RZ diag((ce,-se),(ce,se))
                float2 f0 = make_float2(ce, -se), f1 = make_float2(ce, se);
                e00 = cmul(f0, r00); e01 = cmul(f0, r01);
                e10 = cmul(f1, r10); e11 = cmul(f1, r11);
            }
            lane_bfly(vr, vi, e00.x,e00.y, e01.x,e01.y, e10.x,e10.y, e11.x,e11.y);
        }
        // M(0,1): ctrl q0 (packed: comp0->R, comp1->UR), tgt q1 = bit3
        {
            const float2* Rb = Rq  + (B+0)*4;
            const float2* Ub = URq + (B+0)*4;
            int r = t3 ? 2 : 0;
            float2 Rp = Rb[r], Rqe = Rb[r+1], Up = Ub[r], Uq = Ub[r+1];
            gate_u64(vr, vi, t, 8,
                     pack2(Rp.x, Up.x), pack2(Rp.y, Up.y),
                     pack2(Rqe.x, Uq.x), pack2(Rqe.y, Uq.y));
        }
        if (l <= 3) {  // M(1,2): ctrl bit3, tgt bit2
            const float2* base = (t3 ? URq : Rq) + (B+1)*4;
            int r = t2 ? 2 : 0;
            float2 p = base[r], q = base[r+1];
            gate_u64(vr, vi, t, 4, bc(p.x), bc(p.y), bc(q.x), bc(q.y));
        }
        if (l <= 2) {  // M(2,3): ctrl bit2, tgt bit1
            const float2* base = (t2 ? URq : Rq) + (B+2)*4;
            int r = t1b ? 2 : 0;
            float2 p = base[r], q = base[r+1];
            gate_u64(vr, vi, t, 2, bc(p.x), bc(p.y), bc(q.x), bc(q.y));
        }
        if (l == 1) {  // M(3,4): ctrl bit1, tgt bit0
            const float2* base = (t1b ? URq : Rq) + (B+3)*4;
            int r = t0 ? 2 : 0;
            float2 p = base[r], q = base[r+1];
            gate_u64(vr, vi, t, 1, bc(p.x), bc(p.y), bc(q.x), bc(q.y));
        }
    }

    // ===== Measurement: <Z0>, trailing q0 gate G = H * R40 * R40 (lane-internal)
    {
        float2 r00 = R0f[16], r01 = R0f[17], r10 = R0f[18], r11 = R0f[19];
        float2 s00 = cadd(cmul(r00,r00), cmul(r01,r10));
        float2 s01 = cadd(cmul(r00,r01), cmul(r01,r11));
        float2 s10 = cadd(cmul(r10,r00), cmul(r11,r10));
        float2 s11 = cadd(cmul(r10,r01), cmul(r11,r11));
        float2 g00 = make_float2(R2*(s00.x+s10.x), R2*(s00.y+s10.y));
        float2 g01 = make_float2(R2*(s01.x+s11.x), R2*(s01.y+s11.y));
        float2 g10 = make_float2(R2*(s00.x-s10.x), R2*(s00.y-s10.y));
        float2 g11 = make_float2(R2*(s01.x-s11.x), R2*(s01.y-s11.y));
        lane_bfly(vr, vi, g00.x,g00.y, g01.x,g01.y, g10.x,g10.y, g11.x,g11.y);

        float2 rr = unpk(vr), ii = unpk(vi);
        float z = (rr.x*rr.x + ii.x*ii.x) - (rr.y*rr.y + ii.y*ii.y);
#pragma unroll
        for (int off = 16; off > 0; off >>= 1)
            z += __shfl_down_sync(0xffffffffu, z, off);

        if (t == 0) {   // warp leader: bucketed accumulation (no extra barrier)
            int bucket = (blockIdx.x ^ s) & 7;
            atomicAdd(&g_accB[bucket*16 + s*2 + 0], z * W2[c]);
            atomicAdd(&g_accB[bucket*16 + s*2 + 1], z * W2[NC + c]);
        }
    }
    __syncthreads();

    // last CTA finalizes (16 lanes parallel): sum buckets, softmax, reset
    if (tid == 0) {
        __threadfence();
        lastf = (atomicAdd(&g_done, 1u) == gridDim.x - 1) ? 1u : 0u;
        __threadfence();
    }
    __syncthreads();
    if (lastf) {
        if (tid < 16) {
            float v = b2[tid & 1];
#pragma unroll
            for (int k = 0; k < 8; ++k) v += g_accB[k*16 + tid];
            float o = __shfl_xor_sync(0x0000ffffu, v, 1);
            float m = fmaxf(v, o);
            float e = expf(v - m), eo = expf(o - m);
            out[tid] = e / (e + eo);
        }
        if (tid < 128) g_accB[tid] = 0.0f;
        if (tid == 0) { g_done = 0u; __threadfence(); }
    }
}

extern "C" void kernel_launch(void* const* d_in, const int* in_sizes, int n_in,
                              void* d_out, int out_size) {
    const float* x  = (const float*)d_in[0];   // (8,2)
    const float* W1 = (const float*)d_in[1];   // (320,2)
    const float* b1 = (const float*)d_in[2];   // (320,)
    const float* qw = (const float*)d_in[3];   // (320,5,10,3)
    const float* W2 = (const float*)d_in[4];   // (2,320)
    const float* b2 = (const float*)d_in[5];   // (2,)
    float* out = (float*)d_out;                // (8,2)

    qsim_kernel<<<320, 256>>>(x, W1, b1, qw, W2, b2, out);
}